// round 10
// baseline (speedup 1.0000x reference)
#include <cuda_runtime.h>
#include <cuda_bf16.h>
#include <cuda_fp8.h>
#include <math.h>
#include <stdint.h>

#define BB 32
#define TT_TOT 1500
#define SS 256

typedef __nv_bfloat16 bf16;

// ---------------- scratch buffers (device globals) --------------------------
// fp8 activations
__device__ __align__(16) uint8_t g_a0[BB * SS * 512];
__device__ __align__(16) uint8_t g_a1[BB * SS * 512];
__device__ __align__(16) uint8_t g_c8[BB * SS * 1024];
__device__ __align__(16) uint8_t g_mels8[(size_t)BB * TT_TOT * 128];
__device__ __align__(16) uint8_t g_q08[(size_t)BB * TT_TOT * 256];
__device__ __align__(16) uint8_t g_q18[(size_t)BB * TT_TOT * 128];
// bf16 attention operands
__device__ __align__(16) bf16 g_kT[BB * SS * 96];
__device__ __align__(16) bf16 g_q2T[BB * TT_TOT * 96];
// fp8 weights (repacked, scaled)
__device__ __align__(16) uint8_t g_w0[512 * 2560];
__device__ __align__(16) uint8_t g_w1[512 * 2560];
__device__ __align__(16) uint8_t g_w2[512 * 2560];
__device__ __align__(16) uint8_t g_w3[1024 * 1536];
__device__ __align__(16) uint8_t g_w4[128 * 1024];
__device__ __align__(16) uint8_t g_wq0[256 * 384];
__device__ __align__(16) uint8_t g_wq1[128 * 256];
__device__ __align__(16) uint8_t g_wq2[128 * 128];
__device__ float g_k2v[BB * SS];
__device__ __align__(16) uint8_t g_zero[16];  // zero page

// ---------------- helpers ----------------------------------------------------
__device__ __forceinline__ uint32_t smem_u32(const void* p) {
    uint32_t a;
    asm("{ .reg .u64 t; cvta.to.shared.u64 t, %1; cvt.u32.u64 %0, t; }"
        : "=r"(a) : "l"(p));
    return a;
}
__device__ __forceinline__ void cp16(void* smem, const void* gmem) {
    asm volatile("cp.async.cg.shared.global [%0], [%1], 16;"
                 :: "r"(smem_u32(smem)), "l"(gmem) : "memory");
}
#define CP_COMMIT() asm volatile("cp.async.commit_group;" ::: "memory")
#define CP_WAIT0() asm volatile("cp.async.wait_group 0;" ::: "memory")
#define CP_WAIT1() asm volatile("cp.async.wait_group 1;" ::: "memory")

__device__ __forceinline__ void mma16816(float* d, const uint32_t* a,
                                         const uint32_t* b) {
    asm volatile(
        "mma.sync.aligned.m16n8k16.row.col.f32.bf16.bf16.f32 "
        "{%0,%1,%2,%3}, {%4,%5,%6,%7}, {%8,%9}, {%0,%1,%2,%3};"
        : "+f"(d[0]), "+f"(d[1]), "+f"(d[2]), "+f"(d[3])
        : "r"(a[0]), "r"(a[1]), "r"(a[2]), "r"(a[3]), "r"(b[0]), "r"(b[1]));
}
__device__ __forceinline__ void mma_fp8(float* d, const uint32_t* a,
                                        const uint32_t* b) {
    asm volatile(
        "mma.sync.aligned.m16n8k32.row.col.f32.e4m3.e4m3.f32 "
        "{%0,%1,%2,%3}, {%4,%5,%6,%7}, {%8,%9}, {%0,%1,%2,%3};"
        : "+f"(d[0]), "+f"(d[1]), "+f"(d[2]), "+f"(d[3])
        : "r"(a[0]), "r"(a[1]), "r"(a[2]), "r"(a[3]), "r"(b[0]), "r"(b[1]));
}
__device__ __forceinline__ void ldsm4(uint32_t& r0, uint32_t& r1, uint32_t& r2,
                                      uint32_t& r3, uint32_t addr) {
    asm volatile("ldmatrix.sync.aligned.m8n8.x4.shared.b16 {%0,%1,%2,%3}, [%4];"
                 : "=r"(r0), "=r"(r1), "=r"(r2), "=r"(r3) : "r"(addr));
}
__device__ __forceinline__ uint8_t f2e4(float f) {
    return (uint8_t)__nv_cvt_float_to_fp8(f, __NV_SATFINITE, __NV_E4M3);
}

// ---------------- embedding: a0[b][s][c] fp8 = emb*4096 ---------------------
__global__ void embed_kernel(const int* __restrict__ ph,
                             const float* __restrict__ emb,
                             uint8_t* __restrict__ out) {
    int idx = blockIdx.x * blockDim.x + threadIdx.x;  // 16 fp8 per thread
    if (idx >= BB * SS * 32) return;
    int c16 = idx & 31;
    int s = (idx >> 5) & (SS - 1);
    int b = idx >> 13;
    const float* src = emb + (size_t)ph[b * SS + s] * 512 + c16 * 16;
    uint8_t v[16];
#pragma unroll
    for (int j = 0; j < 16; j += 4) {
        float4 f = *(const float4*)(src + j);
        v[j] = f2e4(f.x * 4096.f); v[j + 1] = f2e4(f.y * 4096.f);
        v[j + 2] = f2e4(f.z * 4096.f); v[j + 3] = f2e4(f.w * 4096.f);
    }
    *(uint4*)(out + (size_t)idx * 16) = *(const uint4*)v;
}

// ------- fused weight repack (fp8, scaled), one launch -----------------------
struct PrepArgs {
    const float* src[8];
    uint8_t* dst[8];
    float wscale[8];
    int Cout[8], Cin[8], KT[8], CINPB[8], total[8];
};
__global__ __launch_bounds__(256) void prep_all(PrepArgs pa) {
    int L = blockIdx.y;
    int idx16 = (blockIdx.x * 256 + threadIdx.x) * 16;
    if (idx16 >= pa.total[L]) return;
    const int CINPB = pa.CINPB[L], KTv = pa.KT[L], Cin = pa.Cin[L],
              Cout = pa.Cout[L];
    const float sw = pa.wscale[L];
    const int Ktot = CINPB * KTv;
    int co = idx16 / Ktot, k = idx16 - co * Ktot;
    int t = k / CINPB, ci = k - t * CINPB;
    const float* w = pa.src[L];
    uint8_t v[16];
#pragma unroll
    for (int j = 0; j < 16; j++) {
        float f = (co < Cout && ci + j < Cin)
                      ? w[((size_t)co * Cin + ci + j) * KTv + t] * sw
                      : 0.f;
        v[j] = f2e4(f);
    }
    *(uint4*)(pa.dst[L] + idx16) = *(const uint4*)v;
}

// ------- mels transpose: mels8[b][t][ci] fp8 = mels*64 (ci padded to 128) ---
__global__ __launch_bounds__(256) void melsT_kernel(const float* __restrict__ mels,
                                                    uint8_t* __restrict__ out) {
    __shared__ float tile[32][33];
    const int b = blockIdx.z;
    const int c0 = blockIdx.y * 32;
    const int t0 = blockIdx.x * 32;
    const int tx = threadIdx.x & 31, ty = threadIdx.x >> 5;
#pragma unroll
    for (int p = 0; p < 4; p++) {
        int c = ty + p * 8;
        tile[c][tx] = (c0 + c < 80 && t0 + tx < TT_TOT)
                          ? mels[((size_t)b * 80 + c0 + c) * TT_TOT + t0 + tx]
                          : 0.f;
    }
    __syncthreads();
#pragma unroll
    for (int p = 0; p < 4; p++) {
        int t = ty + p * 8;
        if (t0 + t < TT_TOT)
            out[((size_t)b * TT_TOT + t0 + t) * 128 + c0 + tx] =
                f2e4(tile[tx][t] * 64.f);
    }
}

// ---------------- fused conv-as-GEMM (FP8 HMMA + ldmatrix, 3-stage) ---------
// All K addressing in BYTES. Chunk = 128 fp8. Row stride 144B (LDSM-safe).
// out = act((acc * INVS) + bias); stored fp8*OSC or bf16.
template <int KTAPS, int CINPB, bool RELU, bool OUTFP8>
__global__ __launch_bounds__(256, 2) void gemm_conv(
    const uint8_t* __restrict__ Aw, const uint8_t* __restrict__ actT,
    const float* __restrict__ bias, void* __restrict__ outT,
    int Cout, int CS, int L, float INVS, float OSC) {
    constexpr int KTOTB = KTAPS * CINPB;
    constexpr int NCH = KTOTB / 128;
    constexpr int PAD = KTAPS / 2;
    constexpr int RPB = 144;
    constexpr int STG = 2 * 128 * RPB;  // bytes per stage (A then B)
    extern __shared__ __align__(16) uint8_t dyn[];

    const int tid = threadIdx.x;
    const int wid = tid >> 5, lane = tid & 31;
    const int wm = wid >> 2, wn = wid & 3;
    const int lr = lane >> 2, lc = (lane & 3) * 2;
    const int b = blockIdx.z, co0 = blockIdx.y * 128, s0 = blockIdx.x * 128;

    const uint8_t* gA = Aw + (size_t)co0 * KTOTB;
    const uint8_t* actB = actT + (size_t)b * L * CINPB;

    const int lmA_off = ((lane & 7) + ((lane >> 3) & 1) * 8) * RPB +
                        (lane >> 4) * 16;
    const int lmB_off = ((lane & 7) + ((lane >> 4) & 1) * 8) * RPB +
                        ((lane >> 3) & 1) * 16;
    const uint32_t aLm0 = smem_u32(dyn + (wm * 64) * RPB + lmA_off);
    const uint32_t bLm0 = smem_u32(dyn + 128 * RPB + (wn * 32) * RPB + lmB_off);

    float acc[4][4][4];
#pragma unroll
    for (int i = 0; i < 4; i++)
#pragma unroll
        for (int j = 0; j < 4; j++)
#pragma unroll
            for (int v = 0; v < 4; v++) acc[i][j][v] = 0.f;

    auto load_chunk = [&](int stg, int ch) {
        const int k0 = ch * 128;
        uint8_t* dA = dyn + stg * STG;
        uint8_t* dB = dA + 128 * RPB;
#pragma unroll
        for (int n = 0; n < 4; n++) {
            int i = tid + n * 256;
            int row = i >> 3, u = i & 7;
            cp16(dA + row * RPB + u * 16, gA + (size_t)row * KTOTB + k0 + u * 16);
        }
#pragma unroll
        for (int n = 0; n < 4; n++) {
            int i = tid + n * 256;
            int row = i >> 3, u = i & 7;
            int kb = k0 + u * 16;
            int t = kb / CINPB;
            int cib = kb - t * CINPB;
            int gs = s0 + row + t - PAD;
            const uint8_t* src = (gs >= 0 && gs < L)
                                     ? actB + (size_t)gs * CINPB + cib
                                     : g_zero;
            cp16(dB + row * RPB + u * 16, src);
        }
        CP_COMMIT();
    };

    load_chunk(0, 0);
    if (NCH > 1) load_chunk(1, 1);

    int st = 0, st2 = 2;
    for (int ch = 0; ch < NCH; ch++) {
        if (ch + 1 < NCH) { CP_WAIT1(); } else { CP_WAIT0(); }
        __syncthreads();
        if (ch + 2 < NCH) load_chunk(st2, ch + 2);
        const uint32_t aB = aLm0 + st * STG;
        const uint32_t bB = bLm0 + st * STG;
#pragma unroll
        for (int kk = 0; kk < 4; kk++) {
            uint32_t af[4][4];
#pragma unroll
            for (int im = 0; im < 4; im++)
                ldsm4(af[im][0], af[im][1], af[im][2], af[im][3],
                      aB + im * 16 * RPB + kk * 32);
            uint32_t bfr[4][2];
#pragma unroll
            for (int h = 0; h < 2; h++)
                ldsm4(bfr[2 * h][0], bfr[2 * h][1], bfr[2 * h + 1][0],
                      bfr[2 * h + 1][1], bB + h * 16 * RPB + kk * 32);
#pragma unroll
            for (int im = 0; im < 4; im++)
#pragma unroll
                for (int in = 0; in < 4; in++)
                    mma_fp8(acc[im][in], af[im], bfr[in]);
        }
        st = (st == 2) ? 0 : st + 1;
        st2 = (st2 == 2) ? 0 : st2 + 1;
    }
    __syncthreads();

    // transposed epilogue
#pragma unroll
    for (int c = 0; c < 2; c++) {
        if (wm == c) {
#pragma unroll
            for (int im = 0; im < 4; im++) {
                int co_loc = im * 16 + lr;
                int gco = co0 + c * 64 + co_loc;
                float b0v = (gco < Cout) ? bias[gco] : 0.f;
                float b1v = (gco + 8 < Cout) ? bias[gco + 8] : 0.f;
#pragma unroll
                for (int in = 0; in < 4; in++) {
                    int sl = wn * 32 + in * 8 + lc;
                    float* d = acc[im][in];
                    float v0 = d[0] * INVS + b0v, v1 = d[1] * INVS + b0v;
                    float v2 = d[2] * INVS + b1v, v3 = d[3] * INVS + b1v;
                    if (RELU) {
                        v0 = fmaxf(v0, 0.f); v1 = fmaxf(v1, 0.f);
                        v2 = fmaxf(v2, 0.f); v3 = fmaxf(v3, 0.f);
                    }
                    if (OUTFP8) {
                        uint8_t* ep8 = dyn;  // 128 x 80 bytes
                        ep8[sl * 80 + co_loc] = f2e4(v0 * OSC);
                        ep8[(sl + 1) * 80 + co_loc] = f2e4(v1 * OSC);
                        ep8[sl * 80 + co_loc + 8] = f2e4(v2 * OSC);
                        ep8[(sl + 1) * 80 + co_loc + 8] = f2e4(v3 * OSC);
                    } else {
                        bf16* ep = (bf16*)dyn;  // 128 x 72 bf16
                        ep[sl * 72 + co_loc] = __float2bfloat16(v0);
                        ep[(sl + 1) * 72 + co_loc] = __float2bfloat16(v1);
                        ep[sl * 72 + co_loc + 8] = __float2bfloat16(v2);
                        ep[(sl + 1) * 72 + co_loc + 8] = __float2bfloat16(v3);
                    }
                }
            }
        }
        __syncthreads();
        int w = CS - (co0 + c * 64);
        if (w > 64) w = 64;
        if (w > 0) {
            if (OUTFP8) {
                uint8_t* outB = (uint8_t*)outT;
                int vpr = w >> 4;
                int tot = 128 * vpr;
                for (int idx = tid; idx < tot; idx += 256) {
                    int s = idx / vpr, v = idx - s * vpr;
                    if (s0 + s < L)
                        *(uint4*)(outB + ((size_t)b * L + s0 + s) * CS + co0 +
                                  c * 64 + v * 16) =
                            *(const uint4*)(dyn + s * 80 + v * 16);
                }
            } else {
                bf16* outB = (bf16*)outT;
                int vpr = w >> 3;
                int tot = 128 * vpr;
                for (int idx = tid; idx < tot; idx += 256) {
                    int s = idx / vpr, v = idx - s * vpr;
                    if (s0 + s < L)
                        *(uint4*)(outB + ((size_t)b * L + s0 + s) * CS + co0 +
                                  c * 64 + v * 8) =
                            *(const uint4*)((bf16*)dyn + s * 72 + v * 8);
                }
            }
        }
        __syncthreads();
    }
}

// ---------------- k squared-norm from kT [b][s][96] -------------------------
__global__ void k2_kernel(const bf16* __restrict__ kT, float* __restrict__ k2) {
    int idx = blockIdx.x * blockDim.x + threadIdx.x;
    if (idx >= BB * SS) return;
    const bf16* p = kT + (size_t)idx * 96;
    float sum = 0.f;
#pragma unroll
    for (int c = 0; c < 96; c++) {
        float v = __bfloat162float(p[c]);
        sum = fmaf(v, v, sum);
    }
    k2[idx] = sum;
}

// ---------------- HMMA attention (bf16): qk + log_softmax + prior + mask ----
__global__ __launch_bounds__(256) void attn_mma(
    const bf16* __restrict__ q2T, const bf16* __restrict__ kT,
    const float* __restrict__ k2, const float* __restrict__ prior,
    const int* __restrict__ mask, float* __restrict__ out) {
    constexpr float TEMP = 0.0005f;
    constexpr int RP = 104;
    extern __shared__ __align__(16) bf16 dynA[];
    bf16* sQ = dynA;
    bf16* sK = dynA + 64 * RP;
    float* k2s = (float*)(dynA + (64 + 256) * RP);
    float* redM = k2s + 256;
    float* redS = redM + 256;
    float* lseS = redS + 256;

    const int tid = threadIdx.x;
    const int wid = tid >> 5, lane = tid & 31;
    const int wm = wid >> 2, wn = wid & 3;
    const int lr = lane >> 2, qq = lane & 3, lc = qq * 2;
    const int b = blockIdx.y, t0 = blockIdx.x * 64;

#pragma unroll
    for (int n = 0; n < 3; n++) {
        int i = tid + n * 256;
        int row = i / 12, u = i % 12;
        int gt = t0 + row;
        const bf16* src = (gt < TT_TOT)
                              ? q2T + ((size_t)b * TT_TOT + gt) * 96 + u * 8
                              : (const bf16*)g_zero;
        cp16(sQ + row * RP + u * 8, src);
    }
#pragma unroll
    for (int n = 0; n < 12; n++) {
        int i = tid + n * 256;
        int row = i / 12, u = i % 12;
        cp16(sK + row * RP + u * 8, kT + ((size_t)b * SS + row) * 96 + u * 8);
    }
    k2s[tid] = k2[b * SS + tid];
    CP_COMMIT();
    CP_WAIT0();
    __syncthreads();

    const int lmA_off = ((lane & 7) + ((lane >> 3) & 1) * 8) * RP +
                        (lane >> 4) * 8;
    const int lmB_off = ((lane & 7) + ((lane >> 4) & 1) * 8) * RP +
                        ((lane >> 3) & 1) * 8;
    const uint32_t aB = smem_u32(sQ + (wm * 32) * RP + lmA_off);
    const uint32_t bB = smem_u32(sK + (wn * 64) * RP + lmB_off);

    float acc[2][8][4];
#pragma unroll
    for (int i = 0; i < 2; i++)
#pragma unroll
        for (int j = 0; j < 8; j++)
#pragma unroll
            for (int v = 0; v < 4; v++) acc[i][j][v] = 0.f;

#pragma unroll
    for (int kk = 0; kk < 6; kk++) {
        uint32_t af[2][4];
#pragma unroll
        for (int im = 0; im < 2; im++)
            ldsm4(af[im][0], af[im][1], af[im][2], af[im][3],
                  aB + (im * 16 * RP + kk * 16) * 2);
        uint32_t bfr[8][2];
#pragma unroll
        for (int h = 0; h < 4; h++)
            ldsm4(bfr[2 * h][0], bfr[2 * h][1], bfr[2 * h + 1][0],
                  bfr[2 * h + 1][1], bB + (h * 16 * RP + kk * 16) * 2);
#pragma unroll
        for (int im = 0; im < 2; im++)
#pragma unroll
            for (int in = 0; in < 8; in++)
                mma16816(acc[im][in], af[im], bfr[in]);
    }

#pragma unroll
    for (int im = 0; im < 2; im++)
#pragma unroll
        for (int in = 0; in < 8; in++) {
            int s = wn * 64 + in * 8 + lc;
            float2 kv = *(float2*)&k2s[s];
            acc[im][in][0] = TEMP * (2.f * acc[im][in][0] - kv.x);
            acc[im][in][1] = TEMP * (2.f * acc[im][in][1] - kv.y);
            acc[im][in][2] = TEMP * (2.f * acc[im][in][2] - kv.x);
            acc[im][in][3] = TEMP * (2.f * acc[im][in][3] - kv.y);
        }

#pragma unroll
    for (int im = 0; im < 2; im++)
#pragma unroll
        for (int h = 0; h < 2; h++) {
            float m = -INFINITY, se = 0.f;
#pragma unroll
            for (int in = 0; in < 8; in++) {
                float v0 = acc[im][in][2 * h], v1 = acc[im][in][2 * h + 1];
                float M = fmaxf(m, fmaxf(v0, v1));
                se = se * __expf(m - M) + __expf(v0 - M) + __expf(v1 - M);
                m = M;
            }
#pragma unroll
            for (int o = 1; o <= 2; o <<= 1) {
                float m2 = __shfl_xor_sync(~0u, m, o);
                float s2 = __shfl_xor_sync(~0u, se, o);
                float M = fmaxf(m, m2);
                se = se * __expf(m - M) + s2 * __expf(m2 - M);
                m = M;
            }
            if (qq == 0) {
                int row = wm * 32 + im * 16 + h * 8 + lr;
                redM[wn * 64 + row] = m;
                redS[wn * 64 + row] = se;
            }
        }
    __syncthreads();
    if (tid < 64) {
        float M = redM[tid], SE = redS[tid];
#pragma unroll
        for (int i = 1; i < 4; i++) {
            float mi = redM[i * 64 + tid], si = redS[i * 64 + tid];
            float Mn = fmaxf(M, mi);
            SE = SE * __expf(M - Mn) + si * __expf(mi - Mn);
            M = Mn;
        }
        lseS[tid] = M + __logf(SE);
    }
    __syncthreads();

#pragma unroll
    for (int im = 0; im < 2; im++)
#pragma unroll
        for (int h = 0; h < 2; h++) {
            int row = wm * 32 + im * 16 + h * 8 + lr;
            int t = t0 + row;
            if (t < TT_TOT) {
                float lse = lseS[row];
                size_t base = ((size_t)b * TT_TOT + t) * SS;
#pragma unroll
                for (int in = 0; in < 8; in++) {
                    int s = wn * 64 + in * 8 + lc;
                    size_t o = base + s;
                    float2 pr = *(const float2*)&prior[o];
                    int2 mk = *(const int2*)&mask[o];
                    float v0 = acc[im][in][2 * h] - lse + __logf(pr.x + 1e-8f);
                    float v1 = acc[im][in][2 * h + 1] - lse + __logf(pr.y + 1e-8f);
                    float2 res;
                    res.x = mk.x ? v0 : -INFINITY;
                    res.y = mk.y ? v1 : -INFINITY;
                    *(float2*)&out[o] = res;
                }
            }
        }
}

// ---------------- launch ----------------------------------------------------
extern "C" void kernel_launch(void* const* d_in, const int* in_sizes, int n_in,
                              void* d_out, int out_size) {
    const int* phonemes = (const int*)d_in[0];
    const float* mels = (const float*)d_in[1];
    const int* mask = (const int*)d_in[2];
    const float* prior = (const float*)d_in[3];
    const float* emb = (const float*)d_in[4];
    const float* kw[5] = {(const float*)d_in[5], (const float*)d_in[7],
                          (const float*)d_in[9], (const float*)d_in[11],
                          (const float*)d_in[13]};
    const float* kb[5] = {(const float*)d_in[6], (const float*)d_in[8],
                          (const float*)d_in[10], (const float*)d_in[12],
                          (const float*)d_in[14]};
    const float* qw[3] = {(const float*)d_in[15], (const float*)d_in[17],
                          (const float*)d_in[19]};
    const float* qb[3] = {(const float*)d_in[16], (const float*)d_in[18],
                          (const float*)d_in[20]};
    float* out = (float*)d_out;

    uint8_t *pA0, *pA1, *pC8, *pM8, *pQ08, *pQ18;
    bf16 *pKT, *pQ2;
    uint8_t* pw[8];
    float* pk2;
    cudaGetSymbolAddress((void**)&pA0, g_a0);
    cudaGetSymbolAddress((void**)&pA1, g_a1);
    cudaGetSymbolAddress((void**)&pC8, g_c8);
    cudaGetSymbolAddress((void**)&pM8, g_mels8);
    cudaGetSymbolAddress((void**)&pQ08, g_q08);
    cudaGetSymbolAddress((void**)&pQ18, g_q18);
    cudaGetSymbolAddress((void**)&pKT, g_kT);
    cudaGetSymbolAddress((void**)&pQ2, g_q2T);
    cudaGetSymbolAddress((void**)&pw[0], g_w0);
    cudaGetSymbolAddress((void**)&pw[1], g_w1);
    cudaGetSymbolAddress((void**)&pw[2], g_w2);
    cudaGetSymbolAddress((void**)&pw[3], g_w3);
    cudaGetSymbolAddress((void**)&pw[4], g_w4);
    cudaGetSymbolAddress((void**)&pw[5], g_wq0);
    cudaGetSymbolAddress((void**)&pw[6], g_wq1);
    cudaGetSymbolAddress((void**)&pw[7], g_wq2);
    cudaGetSymbolAddress((void**)&pk2, g_k2v);

    const int SMG = 3 * 2 * 128 * 144;  // 110592 bytes (3-stage)
    const int SMATT = (64 + 256) * 104 * 2 + (256 * 3 + 64) * 4;
    cudaFuncSetAttribute(gemm_conv<5, 512, true, true>,
                         cudaFuncAttributeMaxDynamicSharedMemorySize, SMG);
    cudaFuncSetAttribute(gemm_conv<3, 512, true, true>,
                         cudaFuncAttributeMaxDynamicSharedMemorySize, SMG);
    cudaFuncSetAttribute(gemm_conv<1, 1024, false, false>,
                         cudaFuncAttributeMaxDynamicSharedMemorySize, SMG);
    cudaFuncSetAttribute(gemm_conv<3, 128, true, true>,
                         cudaFuncAttributeMaxDynamicSharedMemorySize, SMG);
    cudaFuncSetAttribute(gemm_conv<1, 256, true, true>,
                         cudaFuncAttributeMaxDynamicSharedMemorySize, SMG);
    cudaFuncSetAttribute(gemm_conv<1, 128, false, false>,
                         cudaFuncAttributeMaxDynamicSharedMemorySize, SMG);
    cudaFuncSetAttribute(attn_mma,
                         cudaFuncAttributeMaxDynamicSharedMemorySize, SMATT);

    embed_kernel<<<(BB * SS * 32 + 255) / 256, 256>>>(phonemes, emb, pA0);
    melsT_kernel<<<dim3(47, 4, BB), 256>>>(mels, pM8);

    // weight repack: scales 2^14,2^14,2^14,2^13,2^13, 2^12,2^12,2^11
    PrepArgs pa;
    const int CoutA[8] = {512, 512, 512, 1024, 80, 160, 80, 80};
    const int CinA[8] = {512, 512, 512, 512, 1024, 80, 160, 80};
    const int KTA[8] = {5, 5, 5, 3, 1, 3, 1, 1};
    const int CINPA[8] = {512, 512, 512, 512, 1024, 128, 256, 128};
    const int RPAD[8] = {512, 512, 512, 1024, 128, 256, 128, 128};
    const float WS[8] = {16384.f, 16384.f, 16384.f, 8192.f, 8192.f,
                         4096.f, 4096.f, 2048.f};
    const float* srcs[8] = {kw[0], kw[1], kw[2], kw[3], kw[4],
                            qw[0], qw[1], qw[2]};
    for (int i = 0; i < 8; i++) {
        pa.src[i] = srcs[i];
        pa.dst[i] = pw[i];
        pa.wscale[i] = WS[i];
        pa.Cout[i] = CoutA[i];
        pa.Cin[i] = CinA[i];
        pa.KT[i] = KTA[i];
        pa.CINPB[i] = CINPA[i];
        pa.total[i] = RPAD[i] * KTA[i] * CINPA[i];
    }
    prep_all<<<dim3(384, 8), 256>>>(pa);

    // inverse scales: 1/(SA_in * SW)
    const float I0 = 1.f / (4096.f * 16384.f);   // L0-2
    const float I3 = 1.f / (4096.f * 8192.f);    // L3, L4
    const float IQ = 1.f / (64.f * 4096.f);      // q0, q1
    const float IQ2 = 1.f / (64.f * 2048.f);     // q2

    // ---- key encoder (all fp8 in/out except final) ----
    gemm_conv<5, 512, true, true><<<dim3(2, 4, BB), 256, SMG>>>(
        pw[0], pA0, kb[0], pA1, 512, 512, SS, I0, 4096.f);
    gemm_conv<5, 512, true, true><<<dim3(2, 4, BB), 256, SMG>>>(
        pw[1], pA1, kb[1], pA0, 512, 512, SS, I0, 4096.f);
    gemm_conv<5, 512, true, true><<<dim3(2, 4, BB), 256, SMG>>>(
        pw[2], pA0, kb[2], pA1, 512, 512, SS, I0, 4096.f);
    gemm_conv<3, 512, true, true><<<dim3(2, 8, BB), 256, SMG>>>(
        pw[3], pA1, kb[3], pC8, 1024, 1024, SS, I0, 4096.f);
    gemm_conv<1, 1024, false, false><<<dim3(2, 1, BB), 256, SMG>>>(
        pw[4], pC8, kb[4], pKT, 80, 96, SS, I3, 1.f);

    k2_kernel<<<(BB * SS + 255) / 256, 256>>>(pKT, pk2);

    // ---- query encoder ----
    gemm_conv<3, 128, true, true><<<dim3(12, 2, BB), 256, SMG>>>(
        pw[5], pM8, qb[0], pQ08, 160, 256, TT_TOT, IQ, 64.f);
    gemm_conv<1, 256, true, true><<<dim3(12, 1, BB), 256, SMG>>>(
        pw[6], pQ08, qb[1], pQ18, 80, 128, TT_TOT, IQ, 64.f);
    gemm_conv<1, 128, false, false><<<dim3(12, 1, BB), 256, SMG>>>(
        pw[7], pQ18, qb[2], pQ2, 80, 96, TT_TOT, IQ2, 1.f);

    // HMMA attention + log_softmax + prior + mask
    attn_mma<<<dim3((TT_TOT + 63) / 64, BB), 256, SMATT>>>(pQ2, pKT, pk2,
                                                           prior, mask, out);
}